// round 1
// baseline (speedup 1.0000x reference)
#include <cuda_runtime.h>
#include <cstdint>

typedef unsigned long long ull;

#define DIM    64
#define CODES  512
#define NTOK   262144          // 64*64*64 tokens
#define TPB    256
#define NBLK   (NTOK / TPB)    // 1024
#define SROW   68              // floats per code row in smem (64 + pad), 272B = 17x16B
#define SROW_V2 17             // ulonglong2 per code row

// Output layout (float32, concatenated tuple):
// quantize_st[64^4], quant_loss[1], indices[64^3], commitment_loss[1],
// embedding_new[64*512], N_new[512], M_new[64*512]
#define OFF_Q    0L
#define OFF_QL   16777216L
#define OFF_IDX  16777217L
#define OFF_CL   17039361L
#define OFF_EMB  17039362L
#define OFF_N    17072130L
#define OFF_M    17072642L

#define SMEM_BYTES ((CODES*SROW + CODES + TPB) * 4)

__device__ float g_eNorm[CODES];
__device__ float g_ni[CODES];
__device__ float g_eofx[DIM * CODES];
__device__ float g_loss;

// ---- packed f32x2 helpers (ptxas won't auto-fuse; PTX only) ----
__device__ __forceinline__ ull fma2(ull a, ull b, ull c) {
    ull d; asm("fma.rn.f32x2 %0, %1, %2, %3;" : "=l"(d) : "l"(a), "l"(b), "l"(c)); return d;
}
__device__ __forceinline__ ull add2(ull a, ull b) {
    ull d; asm("add.rn.f32x2 %0, %1, %2;" : "=l"(d) : "l"(a), "l"(b)); return d;
}
__device__ __forceinline__ float sum2(ull a) {
    float lo, hi; asm("mov.b64 {%0,%1}, %2;" : "=f"(lo), "=f"(hi) : "l"(a)); return lo + hi;
}
__device__ __forceinline__ void unpack2(ull a, float& lo, float& hi) {
    asm("mov.b64 {%0,%1}, %2;" : "=f"(lo), "=f"(hi) : "l"(a));
}

// ---- kernel 1: zero scratch + codebook column norms ----
__global__ void vq_prep(const float* __restrict__ emb) {
    int tid = blockIdx.x * blockDim.x + threadIdx.x;
    if (tid < DIM * CODES) g_eofx[tid] = 0.f;
    if (tid < CODES) {
        g_ni[tid] = 0.f;
        float s = 0.f;
        #pragma unroll
        for (int d = 0; d < DIM; d++) {
            float v = emb[d * CODES + tid];
            s = fmaf(v, v, s);
        }
        g_eNorm[tid] = s;
    }
    if (tid == 0) g_loss = 0.f;
}

// ---- kernel 2: fused assign / quantize / loss / segment sums ----
extern __shared__ float smem[];

__global__ void __launch_bounds__(TPB, 1)
vq_main(const float* __restrict__ x, const float* __restrict__ emb,
        float* __restrict__ out) {
    float* sE    = smem;                    // [CODES][SROW]
    float* sNorm = sE + CODES * SROW;       // [CODES]
    int*   sIdx  = (int*)(sNorm + CODES);   // [TPB]

    const int tid = threadIdx.x;

    // load embedding transposed: sE[c][d] = emb[d*CODES + c]
    #pragma unroll
    for (int k = 0; k < (DIM * CODES) / TPB; k++) {
        int idx = k * TPB + tid;
        int d = idx >> 9, c = idx & (CODES - 1);
        sE[c * SROW + d] = emb[idx];
    }
    #pragma unroll
    for (int k = 0; k < CODES / TPB; k++) {
        int c = k * TPB + tid;
        sNorm[c] = g_eNorm[c];
    }

    const int token = blockIdx.x * TPB + tid;
    ull xp[32];  // 64 floats packed as f32x2
    {
        const ulonglong2* xg = (const ulonglong2*)(x + (size_t)token * DIM);
        #pragma unroll
        for (int j = 0; j < 16; j++) {
            ulonglong2 v = xg[j];
            xp[2 * j] = v.x; xp[2 * j + 1] = v.y;
        }
    }
    __syncthreads();

    // argmin over codes of  ||e||^2 - 2 x.e   (||x||^2 constant per token)
    float best = 3.402823466e38f;
    int bestc = 0;
    const ulonglong2* ebase = (const ulonglong2*)sE;

    #pragma unroll 1
    for (int c = 0; c < CODES; c += 4) {
        const ulonglong2* e0 = ebase + (size_t)c * SROW_V2;
        const ulonglong2* e1 = e0 + SROW_V2;
        const ulonglong2* e2 = e1 + SROW_V2;
        const ulonglong2* e3 = e2 + SROW_V2;
        ull a0 = 0, b0 = 0, a1 = 0, b1 = 0, a2 = 0, b2 = 0, a3 = 0, b3 = 0;
        #pragma unroll
        for (int j = 0; j < 16; j++) {
            ull xl = xp[2 * j], xh = xp[2 * j + 1];
            ulonglong2 v0 = e0[j], v1 = e1[j], v2 = e2[j], v3 = e3[j];
            a0 = fma2(xl, v0.x, a0); b0 = fma2(xh, v0.y, b0);
            a1 = fma2(xl, v1.x, a1); b1 = fma2(xh, v1.y, b1);
            a2 = fma2(xl, v2.x, a2); b2 = fma2(xh, v2.y, b2);
            a3 = fma2(xl, v3.x, a3); b3 = fma2(xh, v3.y, b3);
        }
        float s0 = sum2(add2(a0, b0));
        float s1 = sum2(add2(a1, b1));
        float s2 = sum2(add2(a2, b2));
        float s3 = sum2(add2(a3, b3));
        float d0 = fmaf(-2.f, s0, sNorm[c]);
        float d1 = fmaf(-2.f, s1, sNorm[c + 1]);
        float d2 = fmaf(-2.f, s2, sNorm[c + 2]);
        float d3 = fmaf(-2.f, s3, sNorm[c + 3]);
        if (d0 < best) { best = d0; bestc = c; }
        if (d1 < best) { best = d1; bestc = c + 1; }
        if (d2 < best) { best = d2; bestc = c + 2; }
        if (d3 < best) { best = d3; bestc = c + 3; }
    }

    sIdx[tid] = bestc;
    out[OFF_IDX + token] = (float)bestc;
    atomicAdd(&g_ni[bestc], 1.0f);

    // loss partial + eofx segment-sum scatter
    float lsum = 0.f;
    const float* eb = sE + bestc * SROW;
    #pragma unroll
    for (int j = 0; j < 32; j++) {
        float x0, x1; unpack2(xp[j], x0, x1);
        float q0 = eb[2 * j], q1 = eb[2 * j + 1];
        float t0 = x0 - q0, t1 = x1 - q1;
        lsum = fmaf(t0, t0, lsum);
        lsum = fmaf(t1, t1, lsum);
        atomicAdd(&g_eofx[(2 * j) * CODES + bestc], x0);
        atomicAdd(&g_eofx[(2 * j + 1) * CODES + bestc], x1);
    }
    #pragma unroll
    for (int o = 16; o > 0; o >>= 1)
        lsum += __shfl_xor_sync(0xffffffffu, lsum, o);
    if ((tid & 31) == 0) atomicAdd(&g_loss, lsum);

    // coalesced quantize_st write (q == quantize numerically)
    __syncthreads();
    const size_t base = (size_t)blockIdx.x * TPB * DIM;
    #pragma unroll 1
    for (int it = 0; it < DIM; it++) {
        int g = it * TPB + tid;
        int t = g >> 6, d = g & 63;
        out[OFF_Q + base + g] = sE[sIdx[t] * SROW + d];
    }
}

// ---- kernel 3: EMA update + smoothing + losses ----
__global__ void vq_finalize(const float* __restrict__ Nin,
                            const float* __restrict__ Min,
                            float* __restrict__ out) {
    __shared__ float red[CODES];
    const int c = threadIdx.x;
    const float DEC = 0.99f, OMD = 1.0f - 0.99f;

    float Nn = fmaf(Nin[c], DEC, OMD * g_ni[c]);
    out[OFF_N + c] = Nn;
    red[c] = Nn;
    __syncthreads();
    for (int s = CODES / 2; s > 0; s >>= 1) {
        if (c < s) red[c] += red[c + s];
        __syncthreads();
    }
    float n = red[0];
    float Ns = (Nn + 1e-5f) / (n + CODES * 1e-5f) * n;

    #pragma unroll
    for (int d = 0; d < DIM; d++) {
        int i = d * CODES + c;
        float Mn = fmaf(Min[i], DEC, OMD * g_eofx[i]);
        out[OFF_M + i] = Mn;
        out[OFF_EMB + i] = Mn / Ns;
    }
    if (c == 0) {
        float l = g_loss * (1.0f / 16777216.0f);
        out[OFF_QL] = l;   // quant_loss
        out[OFF_CL] = l;   // commitment_loss (numerically identical)
    }
}

extern "C" void kernel_launch(void* const* d_in, const int* in_sizes, int n_in,
                              void* d_out, int out_size) {
    const float* x   = (const float*)d_in[0];
    const float* emb = (const float*)d_in[1];
    const float* N   = (const float*)d_in[2];
    const float* M   = (const float*)d_in[3];
    float* out = (float*)d_out;

    cudaFuncSetAttribute(vq_main, cudaFuncAttributeMaxDynamicSharedMemorySize,
                         SMEM_BYTES);

    vq_prep<<<(DIM * CODES + 255) / 256, 256>>>(emb);
    vq_main<<<NBLK, TPB, SMEM_BYTES>>>(x, emb, out);
    vq_finalize<<<1, CODES>>>(N, M, out);
}